// round 11
// baseline (speedup 1.0000x reference)
#include <cuda_runtime.h>
#include <cuda_bf16.h>
#include <math.h>
#include <stdint.h>

#define BATCH 4
#define HW 4096
#define CH 512
#define NGROUP 32
#define CPG 16
#define EPSV 1e-6f

typedef __nv_bfloat16 bf16;

// ---------------- scratch (__device__ globals; allocation-free rule) ----------------
__device__ float g_stats[BATCH * NGROUP * 2];
__device__ __align__(256) bf16 g_xb [BATCH * HW * CH];
__device__ __align__(256) bf16 g_qb [BATCH * HW * CH];
__device__ __align__(256) bf16 g_kb [BATCH * HW * CH];
__device__ __align__(256) bf16 g_vt [BATCH * HW * CH];          // V^T [B][C][N]
__device__ __align__(256) bf16 g_aob[BATCH * HW * CH];
__device__ __align__(256) float g_s [(size_t)BATCH * HW * HW];  // fp32 scores (256 MB)
__device__ __align__(256) bf16 g_pb [(size_t)BATCH * HW * HW];  // bf16 probs (128 MB)
__device__ __align__(256) bf16 g_wqT[CH * CH];
__device__ __align__(256) bf16 g_wkT[CH * CH];
__device__ __align__(256) bf16 g_wvT[CH * CH];
__device__ __align__(256) bf16 g_woT[CH * CH];

// ================= warp-MMA helpers =================
__device__ __forceinline__ uint32_t smem_u32(const void* p) {
    uint32_t a;
    asm("{ .reg .u64 t; cvta.to.shared.u64 t, %1; cvt.u32.u64 %0, t; }" : "=r"(a) : "l"(p));
    return a;
}
__device__ __forceinline__ void cp16(uint32_t saddr, const void* g) {
    asm volatile("cp.async.cg.shared.global [%0], [%1], 16;" :: "r"(saddr), "l"(g));
}
#define CP_COMMIT() asm volatile("cp.async.commit_group;" ::: "memory")
#define CP_WAIT1()  asm volatile("cp.async.wait_group 1;" ::: "memory")

__device__ __forceinline__ void ldsm4(uint32_t (&r)[4], uint32_t addr) {
    asm volatile("ldmatrix.sync.aligned.m8n8.x4.shared.b16 {%0,%1,%2,%3}, [%4];"
                 : "=r"(r[0]), "=r"(r[1]), "=r"(r[2]), "=r"(r[3]) : "r"(addr));
}
__device__ __forceinline__ void mma16816(float* d, const uint32_t* a, const uint32_t* b) {
    asm volatile(
        "mma.sync.aligned.m16n8k16.row.col.f32.bf16.bf16.f32 "
        "{%0,%1,%2,%3}, {%4,%5,%6,%7}, {%8,%9}, {%0,%1,%2,%3};"
        : "+f"(d[0]), "+f"(d[1]), "+f"(d[2]), "+f"(d[3])
        : "r"(a[0]), "r"(a[1]), "r"(a[2]), "r"(a[3]), "r"(b[0]), "r"(b[1]));
}

// smem tile: R rows x 64 bf16 = R x 128B; 8 chunks of 16B per row.
// full-XOR swizzle chunk ^= row&7: conflict-free for STS (2 lanes/row, chunks 0-3/4-7)
// and for ldmatrix 8-row phases (8 distinct 16B banks).
__device__ __forceinline__ uint32_t toff(int r, int c) {
    return (uint32_t)(r * 128 + ((c ^ (r & 7)) << 4));
}

// ================= 128 x BN x 64 three-stage bf16 warp-MMA GEMM =================
// D[128*by + r][BN*bx + c] = sum_k A[r,k] * B[c,k]   (A,B K-major bf16)
// bias_mode: 0 none, 1 per-col, 2 per-row.  v = (acc + bias)*alpha (+res)
template <typename OT, int BN, int WARPS_M>
__global__ void __launch_bounds__(256, 1) wmma_gemm(
    const bf16* __restrict__ A, const bf16* __restrict__ B, OT* __restrict__ C,
    int K, int ldC, long long sA, long long sB, long long sC,
    const float* __restrict__ bias, int bias_mode,
    const float* __restrict__ res, float alpha) {
    constexpr int WARPS_N = 8 / WARPS_M;
    constexpr int WM = 128 / WARPS_M;
    constexpr int WN = BN / WARPS_N;
    constexpr int MF = WM / 16;
    constexpr int ATILE = 128 * 128;            // bytes per A stage (BK=64)
    constexpr int BTILE = BN * 128;             // bytes per B stage
    constexpr int STAGE = ATILE + BTILE;
    constexpr int BRG = BN / 128;               // B row groups per thread pass
    static_assert(WN == 64, "warp N must be 64");
    extern __shared__ __align__(128) unsigned char sm[];

    const int tid = threadIdx.x, wid = tid >> 5, lane = tid & 31;
    const int wm = wid % WARPS_M, wn = wid / WARPS_M;
    const bf16* Ab = A + (size_t)blockIdx.z * sA + (size_t)(blockIdx.y * 128) * K;
    const bf16* Bb = B + (size_t)blockIdx.z * sB + (size_t)(blockIdx.x * BN) * K;
    const uint32_t s0 = smem_u32(sm);

    const int lr = tid >> 1;                    // 0..127
    const int lc4 = (tid & 1) * 4;              // 0 or 4
    uint32_t aoff[4], boff[BRG][4];
#pragma unroll
    for (int i = 0; i < 4; i++) aoff[i] = toff(lr, lc4 + i);
#pragma unroll
    for (int rg = 0; rg < BRG; rg++)
#pragma unroll
        for (int i = 0; i < 4; i++) boff[rg][i] = toff(lr + rg * 128, lc4 + i);

    float acc[MF][8][4];
#pragma unroll
    for (int f = 0; f < MF; f++)
#pragma unroll
        for (int j = 0; j < 8; j++)
#pragma unroll
            for (int e = 0; e < 4; e++) acc[f][j][e] = 0.f;

    const int mid = lane >> 3;
    const int lrow = ((mid & 1) << 3) + (lane & 7);
    const int lchk = mid >> 1;

    const int nt = K >> 6;

    // ---- preload tiles 0 and 1 ----
#pragma unroll
    for (int pt = 0; pt < 2; pt++) {
        const bf16* An = Ab + pt * 64;
        const bf16* Bn = Bb + pt * 64;
        uint32_t d = s0 + pt * STAGE;
#pragma unroll
        for (int i = 0; i < 4; i++)
            cp16(d + aoff[i], An + (size_t)lr * K + ((lc4 + i) << 3));
#pragma unroll
        for (int rg = 0; rg < BRG; rg++)
#pragma unroll
            for (int i = 0; i < 4; i++)
                cp16(d + ATILE + boff[rg][i],
                     Bn + (size_t)(lr + rg * 128) * K + ((lc4 + i) << 3));
        CP_COMMIT();
    }

    int s_cur = 0, s_nxt = 2;
    for (int t = 0; t < nt; t++) {
        CP_WAIT1();                              // tile t resident
        __syncthreads();                         // also guards stage reuse
        if (t + 2 < nt) {
            const bf16* An = Ab + (t + 2) * 64;
            const bf16* Bn = Bb + (t + 2) * 64;
            uint32_t d = s0 + s_nxt * STAGE;
#pragma unroll
            for (int i = 0; i < 4; i++)
                cp16(d + aoff[i], An + (size_t)lr * K + ((lc4 + i) << 3));
#pragma unroll
            for (int rg = 0; rg < BRG; rg++)
#pragma unroll
                for (int i = 0; i < 4; i++)
                    cp16(d + ATILE + boff[rg][i],
                         Bn + (size_t)(lr + rg * 128) * K + ((lc4 + i) << 3));
            CP_COMMIT();
        }
        const uint32_t aB = s0 + s_cur * STAGE;
        const uint32_t bB = aB + ATILE;
#pragma unroll
        for (int s = 0; s < 4; s++) {            // four k16 steps
            uint32_t a[MF][4], b[8][2];
#pragma unroll
            for (int f = 0; f < MF; f++)
                ldsm4(a[f], aB + toff(wm * WM + f * 16 + lrow, s * 2 + lchk));
#pragma unroll
            for (int gq = 0; gq < 4; gq++) {
                uint32_t rr[4];
                ldsm4(rr, bB + toff(wn * 64 + gq * 16 + lrow, s * 2 + lchk));
                b[gq * 2][0] = rr[0]; b[gq * 2][1] = rr[2];
                b[gq * 2 + 1][0] = rr[1]; b[gq * 2 + 1][1] = rr[3];
            }
#pragma unroll
            for (int f = 0; f < MF; f++)
#pragma unroll
                for (int j = 0; j < 8; j++) mma16816(acc[f][j], a[f], b[j]);
        }
        s_cur = (s_cur + 1) % 3;
        s_nxt = (s_nxt + 1) % 3;
    }

    // ---- epilogue ----
    const int g = lane >> 2, t2 = (lane & 3) << 1;
    const int row0 = blockIdx.y * 128 + wm * WM;
    const int col0 = blockIdx.x * BN + wn * WN;
    OT* Cb = C + (size_t)blockIdx.z * sC;
    const float* resb = res ? (res + (size_t)blockIdx.z * sC) : (const float*)0;
#pragma unroll
    for (int f = 0; f < MF; f++) {
#pragma unroll
        for (int j = 0; j < 8; j++) {
            int cc = col0 + j * 8 + t2;
            float bc0 = 0.f, bc1 = 0.f;
            if (bias_mode == 1) { bc0 = bias[cc]; bc1 = bias[cc + 1]; }
#pragma unroll
            for (int h = 0; h < 2; h++) {
                int rr = row0 + f * 16 + g + h * 8;
                float v0 = acc[f][j][h * 2 + 0];
                float v1 = acc[f][j][h * 2 + 1];
                if (bias_mode == 1) { v0 += bc0; v1 += bc1; }
                else if (bias_mode == 2) { float bb = bias[rr]; v0 += bb; v1 += bb; }
                v0 *= alpha; v1 *= alpha;
                size_t o = (size_t)rr * ldC + cc;
                if (resb) { v0 += resb[o]; v1 += resb[o + 1]; }
                if (sizeof(OT) == 4) {
                    *(float2*)((float*)Cb + o) = make_float2(v0, v1);
                } else {
                    __nv_bfloat162 w;
                    w.x = __float2bfloat16(v0); w.y = __float2bfloat16(v1);
                    *(__nv_bfloat162*)((bf16*)Cb + o) = w;
                }
            }
        }
    }
}

// ---------------- GroupNorm stats ----------------
__global__ void gn_stats_kernel(const float* __restrict__ x) {
    int bg = blockIdx.x;
    int b = bg >> 5, g = bg & 31;
    const float* base = x + (size_t)b * HW * CH + g * CPG;
    float s = 0.f, ss = 0.f;
    for (int p = threadIdx.x; p < HW; p += blockDim.x) {
        const float4* r = (const float4*)(base + (size_t)p * CH);
#pragma unroll
        for (int i = 0; i < 4; i++) {
            float4 v = r[i];
            s  += v.x + v.y + v.z + v.w;
            ss += v.x * v.x + v.y * v.y + v.z * v.z + v.w * v.w;
        }
    }
    __shared__ float sh[256], sh2[256];
    int t = threadIdx.x;
    sh[t] = s; sh2[t] = ss;
    __syncthreads();
    for (int o = 128; o > 0; o >>= 1) {
        if (t < o) { sh[t] += sh[t + o]; sh2[t] += sh2[t + o]; }
        __syncthreads();
    }
    if (t == 0) {
        float inv = 1.f / (float)(HW * CPG);
        float mean = sh[0] * inv;
        float var = sh2[0] * inv - mean * mean;
        g_stats[bg * 2]     = mean;
        g_stats[bg * 2 + 1] = rsqrtf(var + EPSV);
    }
}

// ---------------- GroupNorm apply -> bf16 ----------------
__global__ void gn_apply_kernel(const float* __restrict__ x,
                                const float* __restrict__ gamma,
                                const float* __restrict__ beta) {
    size_t i = ((size_t)blockIdx.x * blockDim.x + threadIdx.x) * 4;
    int c = (int)(i % CH);
    int b = (int)(i / ((size_t)HW * CH));
    int bg = b * NGROUP + (c >> 4);
    float mean = g_stats[bg * 2], rstd = g_stats[bg * 2 + 1];
    float4 v  = *(const float4*)(x + i);
    float4 ga = *(const float4*)(gamma + c);
    float4 be = *(const float4*)(beta + c);
    __nv_bfloat162 o01, o23;
    o01.x = __float2bfloat16((v.x - mean) * rstd * ga.x + be.x);
    o01.y = __float2bfloat16((v.y - mean) * rstd * ga.y + be.y);
    o23.x = __float2bfloat16((v.z - mean) * rstd * ga.z + be.z);
    o23.y = __float2bfloat16((v.w - mean) * rstd * ga.w + be.w);
    *(__nv_bfloat162*)(g_xb + i)     = o01;
    *(__nv_bfloat162*)(g_xb + i + 2) = o23;
}

// ---------------- fused 4-way weight transpose fp32 [K,N] -> bf16 [N,K] ----------------
__global__ void transpose_w4_kernel(const float* __restrict__ w0, bf16* __restrict__ d0,
                                    const float* __restrict__ w1, bf16* __restrict__ d1,
                                    const float* __restrict__ w2, bf16* __restrict__ d2,
                                    const float* __restrict__ w3, bf16* __restrict__ d3) {
    const float* w = (blockIdx.z == 0) ? w0 : (blockIdx.z == 1) ? w1
                   : (blockIdx.z == 2) ? w2 : w3;
    bf16* wT       = (blockIdx.z == 0) ? d0 : (blockIdx.z == 1) ? d1
                   : (blockIdx.z == 2) ? d2 : d3;
    __shared__ float t[32][33];
    int c0 = blockIdx.x * 32, dd0 = blockIdx.y * 32;
    int tx = threadIdx.x, ty = threadIdx.y;
#pragma unroll
    for (int r = 0; r < 4; r++) {
        int row = ty + r * 8;
        t[row][tx] = w[(size_t)(c0 + row) * CH + dd0 + tx];
    }
    __syncthreads();
#pragma unroll
    for (int r = 0; r < 4; r++) {
        int row = ty + r * 8;
        wT[(size_t)(dd0 + row) * CH + c0 + tx] = __float2bfloat16(t[tx][row]);
    }
}

// ---------------- row softmax (fp32 in -> bf16 out), vectorized ----------------
__global__ void softmax_kernel(const float* __restrict__ S, bf16* __restrict__ P) {
    size_t row = blockIdx.x;
    const float4* p = (const float4*)(S + row * HW);
    bf16* q = P + row * HW;
    int t = threadIdx.x;
    float4 v[4];
    float m = -1e30f;
#pragma unroll
    for (int i = 0; i < 4; i++) {
        v[i] = p[i * 256 + t];
        m = fmaxf(m, fmaxf(fmaxf(v[i].x, v[i].y), fmaxf(v[i].z, v[i].w)));
    }
    __shared__ float sh[256];
    sh[t] = m; __syncthreads();
    for (int o = 128; o > 0; o >>= 1) { if (t < o) sh[t] = fmaxf(sh[t], sh[t + o]); __syncthreads(); }
    m = sh[0];
    __syncthreads();
    float s = 0.f;
#pragma unroll
    for (int i = 0; i < 4; i++) {
        v[i].x = __expf(v[i].x - m); v[i].y = __expf(v[i].y - m);
        v[i].z = __expf(v[i].z - m); v[i].w = __expf(v[i].w - m);
        s += v[i].x + v[i].y + v[i].z + v[i].w;
    }
    sh[t] = s; __syncthreads();
    for (int o = 128; o > 0; o >>= 1) { if (t < o) sh[t] += sh[t + o]; __syncthreads(); }
    float inv = 1.f / sh[0];
#pragma unroll
    for (int i = 0; i < 4; i++) {
        __nv_bfloat162 a, b;
        a.x = __float2bfloat16(v[i].x * inv); a.y = __float2bfloat16(v[i].y * inv);
        b.x = __float2bfloat16(v[i].z * inv); b.y = __float2bfloat16(v[i].w * inv);
        uint2 pk;
        pk.x = *(uint32_t*)&a; pk.y = *(uint32_t*)&b;
        *(uint2*)(q + (size_t)(i * 256 + t) * 4) = pk;
    }
}

extern "C" void kernel_launch(void* const* d_in, const int* in_sizes, int n_in,
                              void* d_out, int out_size) {
    const float* x     = (const float*)d_in[0];
    const float* gamma = (const float*)d_in[1];
    const float* beta  = (const float*)d_in[2];
    const float* wq    = (const float*)d_in[3];
    const float* bq    = (const float*)d_in[4];
    const float* wk    = (const float*)d_in[5];
    const float* bk    = (const float*)d_in[6];
    const float* wv    = (const float*)d_in[7];
    const float* bv    = (const float*)d_in[8];
    const float* wo    = (const float*)d_in[9];
    const float* bo    = (const float*)d_in[10];
    float* out = (float*)d_out;

    bf16 *pxb, *pqb, *pkb, *pvt, *paob, *ppb;
    bf16 *pwqT, *pwkT, *pwvT, *pwoT;
    float *ps;
    cudaGetSymbolAddress((void**)&pxb,  g_xb);
    cudaGetSymbolAddress((void**)&pqb,  g_qb);
    cudaGetSymbolAddress((void**)&pkb,  g_kb);
    cudaGetSymbolAddress((void**)&pvt,  g_vt);
    cudaGetSymbolAddress((void**)&paob, g_aob);
    cudaGetSymbolAddress((void**)&ppb,  g_pb);
    cudaGetSymbolAddress((void**)&ps,   g_s);
    cudaGetSymbolAddress((void**)&pwqT, g_wqT);
    cudaGetSymbolAddress((void**)&pwkT, g_wkT);
    cudaGetSymbolAddress((void**)&pwvT, g_wvT);
    cudaGetSymbolAddress((void**)&pwoT, g_woT);

    const int SMEM = 3 * (128 * 128 + 256 * 128);   // 147456 B
    cudaFuncSetAttribute(wmma_gemm<bf16, 256, 2>,
                         cudaFuncAttributeMaxDynamicSharedMemorySize, SMEM);
    cudaFuncSetAttribute(wmma_gemm<float, 256, 2>,
                         cudaFuncAttributeMaxDynamicSharedMemorySize, SMEM);

    // GroupNorm
    gn_stats_kernel<<<BATCH * NGROUP, 256>>>(x);
    gn_apply_kernel<<<(BATCH * HW * CH / 4) / 256, 256>>>(x, gamma, beta);

    // fused weight transposes (K-major bf16)
    transpose_w4_kernel<<<dim3(16, 16, 4), dim3(32, 8)>>>(
        wq, pwqT, wk, pwkT, wv, pwvT, wo, pwoT);

    const float scale = 0.0441941738241592f;  // 1/sqrt(512)

    // Q/K projections: [16384 x 512] x [512 x 512]
    dim3 gproj(CH / 256, (BATCH * HW) / 128, 1);  // (2, 128)
    wmma_gemm<bf16, 256, 2><<<gproj, 256, SMEM>>>(pxb, pwqT, pqb, CH, CH, 0, 0, 0,
                                                  bq, 1, 0, scale);
    wmma_gemm<bf16, 256, 2><<<gproj, 256, SMEM>>>(pxb, pwkT, pkb, CH, CH, 0, 0, 0,
                                                  bk, 1, 0, 1.f);

    // V^T directly: vt[c][n] = sum_k wvT[c,k] * xb[n,k]  (bias per row c)
    dim3 gvt(HW / 256, CH / 128, BATCH);          // (16, 4, 4)
    wmma_gemm<bf16, 256, 2><<<gvt, 256, SMEM>>>(pwvT, pxb, pvt, CH, HW,
                                                0, (long long)HW * CH, (long long)CH * HW,
                                                bv, 2, 0, 1.f);

    // scores: per batch [4096 x 512] x [4096 x 512]^T -> fp32
    dim3 gsc(HW / 256, HW / 128, BATCH);          // (16, 32, 4)
    wmma_gemm<float, 256, 2><<<gsc, 256, SMEM>>>(pqb, pkb, ps, CH, HW,
                                                 (long long)HW * CH, (long long)HW * CH,
                                                 (long long)HW * HW, 0, 0, 0, 1.f);

    softmax_kernel<<<BATCH * HW, 256>>>(ps, ppb);

    // AV: per batch [4096 x 4096] x [512 x 4096]^T -> bf16
    dim3 gav(CH / 256, HW / 128, BATCH);          // (2, 32, 4)
    wmma_gemm<bf16, 256, 2><<<gav, 256, SMEM>>>(ppb, pvt, paob, HW, CH,
                                                (long long)HW * HW, (long long)CH * HW,
                                                (long long)HW * CH, 0, 0, 0, 1.f);

    // out projection + residual -> fp32 out
    wmma_gemm<float, 256, 2><<<gproj, 256, SMEM>>>(paob, pwoT, out, CH, CH, 0, 0, 0,
                                                   bo, 1, x, 1.f);
}

// round 12
// speedup vs baseline: 1.7376x; 1.7376x over previous
#include <cuda_runtime.h>
#include <cuda_bf16.h>
#include <math.h>
#include <stdint.h>

#define BATCH 4
#define HW 4096
#define CH 512
#define NGROUP 32
#define CPG 16
#define EPSV 1e-6f

typedef __nv_bfloat16 bf16;

// ---------------- scratch (__device__ globals; allocation-free rule) ----------------
__device__ float g_stats[BATCH * NGROUP * 2];
__device__ __align__(256) bf16 g_xb [BATCH * HW * CH];
__device__ __align__(256) bf16 g_qb [BATCH * HW * CH];
__device__ __align__(256) bf16 g_kb [BATCH * HW * CH];
__device__ __align__(256) bf16 g_vt [BATCH * HW * CH];          // V^T [B][C][N]
__device__ __align__(256) bf16 g_aob[BATCH * HW * CH];
__device__ __align__(256) float g_s [(size_t)BATCH * HW * HW];  // fp32 scores (256 MB)
__device__ __align__(256) bf16 g_pb [(size_t)BATCH * HW * HW];  // bf16 probs (128 MB)
__device__ __align__(256) bf16 g_wqT[CH * CH];
__device__ __align__(256) bf16 g_wkT[CH * CH];
__device__ __align__(256) bf16 g_wvT[CH * CH];
__device__ __align__(256) bf16 g_woT[CH * CH];

// ================= warp-MMA helpers =================
__device__ __forceinline__ uint32_t smem_u32(const void* p) {
    uint32_t a;
    asm("{ .reg .u64 t; cvta.to.shared.u64 t, %1; cvt.u32.u64 %0, t; }" : "=r"(a) : "l"(p));
    return a;
}
__device__ __forceinline__ void cp16(uint32_t saddr, const void* g) {
    asm volatile("cp.async.cg.shared.global [%0], [%1], 16;" :: "r"(saddr), "l"(g));
}
#define CP_COMMIT() asm volatile("cp.async.commit_group;" ::: "memory")
#define CP_WAIT2()  asm volatile("cp.async.wait_group 2;" ::: "memory")

__device__ __forceinline__ void ldsm4(uint32_t (&r)[4], uint32_t addr) {
    asm volatile("ldmatrix.sync.aligned.m8n8.x4.shared.b16 {%0,%1,%2,%3}, [%4];"
                 : "=r"(r[0]), "=r"(r[1]), "=r"(r[2]), "=r"(r[3]) : "r"(addr));
}
__device__ __forceinline__ void mma16816(float* d, const uint32_t* a, const uint32_t* b) {
    asm volatile(
        "mma.sync.aligned.m16n8k16.row.col.f32.bf16.bf16.f32 "
        "{%0,%1,%2,%3}, {%4,%5,%6,%7}, {%8,%9}, {%0,%1,%2,%3};"
        : "+f"(d[0]), "+f"(d[1]), "+f"(d[2]), "+f"(d[3])
        : "r"(a[0]), "r"(a[1]), "r"(a[2]), "r"(a[3]), "r"(b[0]), "r"(b[1]));
}

// smem tile: R rows x 32 bf16 = R x 64B; 4 chunks of 16B per row,
// chunk swizzle c ^= (row>>1)&3  (conflict-free for STS and ldmatrix; verified R7/R9)
__device__ __forceinline__ uint32_t tile_off(int r, int c) {
    return (uint32_t)(r * 64 + ((c ^ ((r >> 1) & 3)) << 4));
}

// ================= 128 x BN x 32, 4-stage pipelined bf16 warp-MMA GEMM =================
// D[128*by + r][BN*bx + c] = sum_k A[r,k] * B[c,k]   (A,B K-major bf16)
// bias_mode: 0 none, 1 per-col, 2 per-row.  v = (acc + bias)*alpha (+res)
template <typename OT, int BN, int WARPS_M>
__global__ void __launch_bounds__(256, 1) wmma_gemm(
    const bf16* __restrict__ A, const bf16* __restrict__ B, OT* __restrict__ C,
    int K, int ldC, long long sA, long long sB, long long sC,
    const float* __restrict__ bias, int bias_mode,
    const float* __restrict__ res, float alpha) {
    constexpr int WARPS_N = 8 / WARPS_M;
    constexpr int WM = 128 / WARPS_M;
    constexpr int WN = BN / WARPS_N;
    constexpr int MF = WM / 16;
    constexpr int ATILE = 128 * 64;             // bytes per A stage (BK=32)
    constexpr int BTILE = BN * 64;              // bytes per B stage
    constexpr int STAGE = ATILE + BTILE;
    static_assert(WN == 64, "warp N must be 64");
    extern __shared__ __align__(128) unsigned char sm[];

    const int tid = threadIdx.x, wid = tid >> 5, lane = tid & 31;
    const int wm = wid % WARPS_M, wn = wid / WARPS_M;
    const bf16* Ab = A + (size_t)blockIdx.z * sA + (size_t)(blockIdx.y * 128) * K;
    const bf16* Bb = B + (size_t)blockIdx.z * sB + (size_t)(blockIdx.x * BN) * K;
    const uint32_t s0 = smem_u32(sm);

    const int lr = tid >> 2, lc = tid & 3;      // linear row 0..63(x2), chunk
    const uint32_t so0 = tile_off(lr, lc);
    const uint32_t so1 = tile_off(lr + 64, lc);
    const uint32_t gcol = (uint32_t)(lc << 3);

    float acc[MF][8][4];
#pragma unroll
    for (int f = 0; f < MF; f++)
#pragma unroll
        for (int j = 0; j < 8; j++)
#pragma unroll
            for (int e = 0; e < 4; e++) acc[f][j][e] = 0.f;

    const int mid = lane >> 3;
    const int lrow = ((mid & 1) << 3) + (lane & 7);
    const int lchk = mid >> 1;

    const int nt = K >> 5;

    // ---- preload tiles 0,1,2 (one commit each) ----
#pragma unroll
    for (int pt = 0; pt < 3; pt++) {
        const bf16* An = Ab + pt * 32;
        const bf16* Bn = Bb + pt * 32;
        uint32_t d = s0 + pt * STAGE;
        cp16(d + so0, An + (size_t)lr * K + gcol);
        cp16(d + so1, An + (size_t)(lr + 64) * K + gcol);
        cp16(d + ATILE + so0, Bn + (size_t)lr * K + gcol);
        cp16(d + ATILE + so1, Bn + (size_t)(lr + 64) * K + gcol);
        if (BN == 256) {
            cp16(d + ATILE + tile_off(lr + 128, lc), Bn + (size_t)(lr + 128) * K + gcol);
            cp16(d + ATILE + tile_off(lr + 192, lc), Bn + (size_t)(lr + 192) * K + gcol);
        }
        CP_COMMIT();
    }

    for (int t = 0; t < nt; t++) {
        CP_WAIT2();                              // tile t resident (3 newest pending max)
        __syncthreads();                         // t visible to all; t-1 compute done
        if (t + 3 < nt) {
            const bf16* An = Ab + (t + 3) * 32;
            const bf16* Bn = Bb + (t + 3) * 32;
            uint32_t d = s0 + ((t + 3) & 3) * STAGE;
            cp16(d + so0, An + (size_t)lr * K + gcol);
            cp16(d + so1, An + (size_t)(lr + 64) * K + gcol);
            cp16(d + ATILE + so0, Bn + (size_t)lr * K + gcol);
            cp16(d + ATILE + so1, Bn + (size_t)(lr + 64) * K + gcol);
            if (BN == 256) {
                cp16(d + ATILE + tile_off(lr + 128, lc), Bn + (size_t)(lr + 128) * K + gcol);
                cp16(d + ATILE + tile_off(lr + 192, lc), Bn + (size_t)(lr + 192) * K + gcol);
            }
        }
        CP_COMMIT();                             // always: keeps group accounting uniform
        const uint32_t aB = s0 + (t & 3) * STAGE;
        const uint32_t bB = aB + ATILE;
#pragma unroll
        for (int s = 0; s < 2; s++) {            // two k16 steps
            uint32_t a[MF][4], b[8][2];
#pragma unroll
            for (int f = 0; f < MF; f++)
                ldsm4(a[f], aB + tile_off(wm * WM + f * 16 + lrow, s * 2 + lchk));
#pragma unroll
            for (int gq = 0; gq < 4; gq++) {
                uint32_t rr[4];
                ldsm4(rr, bB + tile_off(wn * 64 + gq * 16 + lrow, s * 2 + lchk));
                b[gq * 2][0] = rr[0]; b[gq * 2][1] = rr[2];
                b[gq * 2 + 1][0] = rr[1]; b[gq * 2 + 1][1] = rr[3];
            }
#pragma unroll
            for (int f = 0; f < MF; f++)
#pragma unroll
                for (int j = 0; j < 8; j++) mma16816(acc[f][j], a[f], b[j]);
        }
    }

    // ---- epilogue ----
    const int g = lane >> 2, t2 = (lane & 3) << 1;
    const int row0 = blockIdx.y * 128 + wm * WM;
    const int col0 = blockIdx.x * BN + wn * WN;
    OT* Cb = C + (size_t)blockIdx.z * sC;
    const float* resb = res ? (res + (size_t)blockIdx.z * sC) : (const float*)0;
#pragma unroll
    for (int f = 0; f < MF; f++) {
#pragma unroll
        for (int j = 0; j < 8; j++) {
            int cc = col0 + j * 8 + t2;
            float bc0 = 0.f, bc1 = 0.f;
            if (bias_mode == 1) { bc0 = bias[cc]; bc1 = bias[cc + 1]; }
#pragma unroll
            for (int h = 0; h < 2; h++) {
                int rr = row0 + f * 16 + g + h * 8;
                float v0 = acc[f][j][h * 2 + 0];
                float v1 = acc[f][j][h * 2 + 1];
                if (bias_mode == 1) { v0 += bc0; v1 += bc1; }
                else if (bias_mode == 2) { float bb = bias[rr]; v0 += bb; v1 += bb; }
                v0 *= alpha; v1 *= alpha;
                size_t o = (size_t)rr * ldC + cc;
                if (resb) { v0 += resb[o]; v1 += resb[o + 1]; }
                if (sizeof(OT) == 4) {
                    *(float2*)((float*)Cb + o) = make_float2(v0, v1);
                } else {
                    __nv_bfloat162 w;
                    w.x = __float2bfloat16(v0); w.y = __float2bfloat16(v1);
                    *(__nv_bfloat162*)((bf16*)Cb + o) = w;
                }
            }
        }
    }
}

// ---------------- GroupNorm stats ----------------
__global__ void gn_stats_kernel(const float* __restrict__ x) {
    int bg = blockIdx.x;
    int b = bg >> 5, g = bg & 31;
    const float* base = x + (size_t)b * HW * CH + g * CPG;
    float s = 0.f, ss = 0.f;
    for (int p = threadIdx.x; p < HW; p += blockDim.x) {
        const float4* r = (const float4*)(base + (size_t)p * CH);
#pragma unroll
        for (int i = 0; i < 4; i++) {
            float4 v = r[i];
            s  += v.x + v.y + v.z + v.w;
            ss += v.x * v.x + v.y * v.y + v.z * v.z + v.w * v.w;
        }
    }
    __shared__ float sh[256], sh2[256];
    int t = threadIdx.x;
    sh[t] = s; sh2[t] = ss;
    __syncthreads();
    for (int o = 128; o > 0; o >>= 1) {
        if (t < o) { sh[t] += sh[t + o]; sh2[t] += sh2[t + o]; }
        __syncthreads();
    }
    if (t == 0) {
        float inv = 1.f / (float)(HW * CPG);
        float mean = sh[0] * inv;
        float var = sh2[0] * inv - mean * mean;
        g_stats[bg * 2]     = mean;
        g_stats[bg * 2 + 1] = rsqrtf(var + EPSV);
    }
}

// ---------------- GroupNorm apply -> bf16 ----------------
__global__ void gn_apply_kernel(const float* __restrict__ x,
                                const float* __restrict__ gamma,
                                const float* __restrict__ beta) {
    size_t i = ((size_t)blockIdx.x * blockDim.x + threadIdx.x) * 4;
    int c = (int)(i % CH);
    int b = (int)(i / ((size_t)HW * CH));
    int bg = b * NGROUP + (c >> 4);
    float mean = g_stats[bg * 2], rstd = g_stats[bg * 2 + 1];
    float4 v  = *(const float4*)(x + i);
    float4 ga = *(const float4*)(gamma + c);
    float4 be = *(const float4*)(beta + c);
    __nv_bfloat162 o01, o23;
    o01.x = __float2bfloat16((v.x - mean) * rstd * ga.x + be.x);
    o01.y = __float2bfloat16((v.y - mean) * rstd * ga.y + be.y);
    o23.x = __float2bfloat16((v.z - mean) * rstd * ga.z + be.z);
    o23.y = __float2bfloat16((v.w - mean) * rstd * ga.w + be.w);
    *(__nv_bfloat162*)(g_xb + i)     = o01;
    *(__nv_bfloat162*)(g_xb + i + 2) = o23;
}

// ---------------- fused 4-way weight transpose fp32 [K,N] -> bf16 [N,K] ----------------
__global__ void transpose_w4_kernel(const float* __restrict__ w0, bf16* __restrict__ d0,
                                    const float* __restrict__ w1, bf16* __restrict__ d1,
                                    const float* __restrict__ w2, bf16* __restrict__ d2,
                                    const float* __restrict__ w3, bf16* __restrict__ d3) {
    const float* w = (blockIdx.z == 0) ? w0 : (blockIdx.z == 1) ? w1
                   : (blockIdx.z == 2) ? w2 : w3;
    bf16* wT       = (blockIdx.z == 0) ? d0 : (blockIdx.z == 1) ? d1
                   : (blockIdx.z == 2) ? d2 : d3;
    __shared__ float t[32][33];
    int c0 = blockIdx.x * 32, dd0 = blockIdx.y * 32;
    int tx = threadIdx.x, ty = threadIdx.y;
#pragma unroll
    for (int r = 0; r < 4; r++) {
        int row = ty + r * 8;
        t[row][tx] = w[(size_t)(c0 + row) * CH + dd0 + tx];
    }
    __syncthreads();
#pragma unroll
    for (int r = 0; r < 4; r++) {
        int row = ty + r * 8;
        wT[(size_t)(dd0 + row) * CH + c0 + tx] = __float2bfloat16(t[tx][row]);
    }
}

// ---------------- row softmax (fp32 in -> bf16 out), vectorized ----------------
__global__ void softmax_kernel(const float* __restrict__ S, bf16* __restrict__ P) {
    size_t row = blockIdx.x;
    const float4* p = (const float4*)(S + row * HW);
    bf16* q = P + row * HW;
    int t = threadIdx.x;
    float4 v[4];
    float m = -1e30f;
#pragma unroll
    for (int i = 0; i < 4; i++) {
        v[i] = p[i * 256 + t];
        m = fmaxf(m, fmaxf(fmaxf(v[i].x, v[i].y), fmaxf(v[i].z, v[i].w)));
    }
    __shared__ float sh[256];
    sh[t] = m; __syncthreads();
    for (int o = 128; o > 0; o >>= 1) { if (t < o) sh[t] = fmaxf(sh[t], sh[t + o]); __syncthreads(); }
    m = sh[0];
    __syncthreads();
    float s = 0.f;
#pragma unroll
    for (int i = 0; i < 4; i++) {
        v[i].x = __expf(v[i].x - m); v[i].y = __expf(v[i].y - m);
        v[i].z = __expf(v[i].z - m); v[i].w = __expf(v[i].w - m);
        s += v[i].x + v[i].y + v[i].z + v[i].w;
    }
    sh[t] = s; __syncthreads();
    for (int o = 128; o > 0; o >>= 1) { if (t < o) sh[t] += sh[t + o]; __syncthreads(); }
    float inv = 1.f / sh[0];
#pragma unroll
    for (int i = 0; i < 4; i++) {
        __nv_bfloat162 a, b;
        a.x = __float2bfloat16(v[i].x * inv); a.y = __float2bfloat16(v[i].y * inv);
        b.x = __float2bfloat16(v[i].z * inv); b.y = __float2bfloat16(v[i].w * inv);
        uint2 pk;
        pk.x = *(uint32_t*)&a; pk.y = *(uint32_t*)&b;
        *(uint2*)(q + (size_t)(i * 256 + t) * 4) = pk;
    }
}

extern "C" void kernel_launch(void* const* d_in, const int* in_sizes, int n_in,
                              void* d_out, int out_size) {
    const float* x     = (const float*)d_in[0];
    const float* gamma = (const float*)d_in[1];
    const float* beta  = (const float*)d_in[2];
    const float* wq    = (const float*)d_in[3];
    const float* bq    = (const float*)d_in[4];
    const float* wk    = (const float*)d_in[5];
    const float* bk    = (const float*)d_in[6];
    const float* wv    = (const float*)d_in[7];
    const float* bv    = (const float*)d_in[8];
    const float* wo    = (const float*)d_in[9];
    const float* bo    = (const float*)d_in[10];
    float* out = (float*)d_out;

    bf16 *pxb, *pqb, *pkb, *pvt, *paob, *ppb;
    bf16 *pwqT, *pwkT, *pwvT, *pwoT;
    float *ps;
    cudaGetSymbolAddress((void**)&pxb,  g_xb);
    cudaGetSymbolAddress((void**)&pqb,  g_qb);
    cudaGetSymbolAddress((void**)&pkb,  g_kb);
    cudaGetSymbolAddress((void**)&pvt,  g_vt);
    cudaGetSymbolAddress((void**)&paob, g_aob);
    cudaGetSymbolAddress((void**)&ppb,  g_pb);
    cudaGetSymbolAddress((void**)&ps,   g_s);
    cudaGetSymbolAddress((void**)&pwqT, g_wqT);
    cudaGetSymbolAddress((void**)&pwkT, g_wkT);
    cudaGetSymbolAddress((void**)&pwvT, g_wvT);
    cudaGetSymbolAddress((void**)&pwoT, g_woT);

    const int SMEM = 4 * (128 * 64 + 256 * 64);   // 98304 B
    cudaFuncSetAttribute(wmma_gemm<bf16, 256, 2>,
                         cudaFuncAttributeMaxDynamicSharedMemorySize, SMEM);
    cudaFuncSetAttribute(wmma_gemm<float, 256, 2>,
                         cudaFuncAttributeMaxDynamicSharedMemorySize, SMEM);

    // GroupNorm
    gn_stats_kernel<<<BATCH * NGROUP, 256>>>(x);
    gn_apply_kernel<<<(BATCH * HW * CH / 4) / 256, 256>>>(x, gamma, beta);

    // fused weight transposes (K-major bf16)
    transpose_w4_kernel<<<dim3(16, 16, 4), dim3(32, 8)>>>(
        wq, pwqT, wk, pwkT, wv, pwvT, wo, pwoT);

    const float scale = 0.0441941738241592f;  // 1/sqrt(512)

    // Q/K projections: [16384 x 512] x [512 x 512]
    dim3 gproj(CH / 256, (BATCH * HW) / 128, 1);  // (2, 128)
    wmma_gemm<bf16, 256, 2><<<gproj, 256, SMEM>>>(pxb, pwqT, pqb, CH, CH, 0, 0, 0,
                                                  bq, 1, 0, scale);
    wmma_gemm<bf16, 256, 2><<<gproj, 256, SMEM>>>(pxb, pwkT, pkb, CH, CH, 0, 0, 0,
                                                  bk, 1, 0, 1.f);

    // V^T directly: vt[c][n] = sum_k wvT[c,k] * xb[n,k]  (bias per row c)
    dim3 gvt(HW / 256, CH / 128, BATCH);          // (16, 4, 4)
    wmma_gemm<bf16, 256, 2><<<gvt, 256, SMEM>>>(pwvT, pxb, pvt, CH, HW,
                                                0, (long long)HW * CH, (long long)CH * HW,
                                                bv, 2, 0, 1.f);

    // scores: per batch [4096 x 512] x [4096 x 512]^T -> fp32
    dim3 gsc(HW / 256, HW / 128, BATCH);          // (16, 32, 4)
    wmma_gemm<float, 256, 2><<<gsc, 256, SMEM>>>(pqb, pkb, ps, CH, HW,
                                                 (long long)HW * CH, (long long)HW * CH,
                                                 (long long)HW * HW, 0, 0, 0, 1.f);

    softmax_kernel<<<BATCH * HW, 256>>>(ps, ppb);

    // AV: per batch [4096 x 4096] x [512 x 4096]^T -> bf16
    dim3 gav(CH / 256, HW / 128, BATCH);          // (2, 32, 4)
    wmma_gemm<bf16, 256, 2><<<gav, 256, SMEM>>>(ppb, pvt, paob, HW, CH,
                                                (long long)HW * HW, (long long)CH * HW,
                                                (long long)HW * CH, 0, 0, 0, 1.f);

    // out projection + residual -> fp32 out
    wmma_gemm<float, 256, 2><<<gproj, 256, SMEM>>>(paob, pwoT, out, CH, CH, 0, 0, 0,
                                                   bo, 1, x, 1.f);
}